// round 13
// baseline (speedup 1.0000x reference)
#include <cuda_runtime.h>
#include <cuda_fp16.h>
#include <cstdint>

// ---------------------------------------------------------------------------
// LightGCN on B200 (sm_100a) — CSR-gather, fp16 folded-weight states,
// 16-lane/row uint2 gathers, full-batch-unrolled inner loop.
//   Trick: store x'[c] = dis[c]*x[c] (fp16). Gather = pure sum S = sum x'[col].
//   y'_{l+1}[r] = dis[r]^2 * S. Epilogue: x_l[r] = idis[r]*y'_l[r].
//   CSR holds only col (4 B/edge). Math fp32; storage fp16.
// ---------------------------------------------------------------------------

#define NUM_USERS   100000
#define NUM_ST      150000
#define NUM_INTENTS 6000
#define N_NODES     (NUM_USERS + NUM_ST + NUM_INTENTS)   // 256000
#define EMBED_DIM   64
#define N_EDGES     4000000

#define NFLOATS     (N_NODES * EMBED_DIM)        // 16,384,000
#define NF4         (NFLOATS / 4)                // 4,096,000
#define DETECT_N    4096

#define SCAN_BLOCK  1024
#define NBLK        (N_NODES / SCAN_BLOCK)       // 250 (exact)

// half2 <-> u32 reinterpret helpers
__device__ __forceinline__ unsigned h2u(__half2 h) {
    return *reinterpret_cast<unsigned*>(&h);
}
__device__ __forceinline__ __half2 u2h(unsigned u) {
    return *reinterpret_cast<__half2*>(&u);
}

// Scratch (device globals: allocation-guard safe)
__device__ __align__(16) __half g_e [NFLOATS];   // emb' = dis*emb   (fp16)
__device__ __align__(16) __half g_h1[NFLOATS];   // y1' = dis*x1     (fp16)
__device__ __align__(16) __half g_h2[NFLOATS];   // y2' = dis*x2     (fp16)
__device__ float g_dis [N_NODES];    // deg^-1/2 (0 if deg==0)
__device__ float g_idis[N_NODES];    // deg^+1/2 (0 if deg==0)
__device__ int   g_deg[N_NODES];
__device__ int   g_start[N_NODES];     // CSR row start (exclusive scan)
__device__ int   g_cursor[N_NODES];    // fill cursor; after fill = row end
__device__ int   g_bsum[NBLK];
__device__ int   g_bsumx[NBLK];
__device__ int   g_csr_col[N_EDGES];   // col only (4 B/edge)
__device__ int   g_not64;   // 1 => edge data is int32 (zeroed via memset)

// ---------------------------------------------------------------------------

// Zero degrees + dtype detection (g_not64 pre-zeroed by cudaMemsetAsync).
// Genuine int64 indices all lie in [0, N_NODES); int32 data read as int64
// fuses two indices -> value >= 2^32 almost surely.
__global__ void k_zero_detect(const long long* __restrict__ ei) {
    int i = blockIdx.x * blockDim.x + threadIdx.x;
    if (i < N_NODES) g_deg[i] = 0;
    if (i < DETECT_N) {
        long long v = ei[i];
        if (v < 0 || v >= N_NODES) atomicOr(&g_not64, 1);
    }
}

// Degree histogram straight from edge_index (row half only).
__global__ void k_deg(const void* __restrict__ eiv) {
    int e = blockIdx.x * blockDim.x + threadIdx.x;
    if (e >= N_EDGES) return;
    long long r64;
    if (g_not64) r64 = ((const int*)eiv)[e];
    else         r64 = ((const long long*)eiv)[e];
    if (r64 >= 0 && r64 < N_NODES) atomicAdd(&g_deg[(int)r64], 1);
}

// ---- exclusive prefix sum over g_deg ----

__global__ void k_scan1() {
    __shared__ int sh[SCAN_BLOCK];
    int i = blockIdx.x * SCAN_BLOCK + threadIdx.x;
    int v = g_deg[i];
    sh[threadIdx.x] = v;
    __syncthreads();
    for (int off = 1; off < SCAN_BLOCK; off <<= 1) {
        int t = (threadIdx.x >= off) ? sh[threadIdx.x - off] : 0;
        __syncthreads();
        sh[threadIdx.x] += t;
        __syncthreads();
    }
    g_start[i] = sh[threadIdx.x];   // inclusive-within-block (temp)
    if (threadIdx.x == SCAN_BLOCK - 1) g_bsum[blockIdx.x] = sh[threadIdx.x];
}

__global__ void k_scan2() {   // single block of 256 threads, NBLK=250
    __shared__ int sh[256];
    int v = (threadIdx.x < NBLK) ? g_bsum[threadIdx.x] : 0;
    sh[threadIdx.x] = v;
    __syncthreads();
    for (int off = 1; off < 256; off <<= 1) {
        int t = (threadIdx.x >= off) ? sh[threadIdx.x - off] : 0;
        __syncthreads();
        sh[threadIdx.x] += t;
        __syncthreads();
    }
    if (threadIdx.x < NBLK) g_bsumx[threadIdx.x] = sh[threadIdx.x] - v; // exclusive
}

// scan fixup + dis/idis (merged; deg already at hand)
__global__ void k_scan3() {
    int i = blockIdx.x * blockDim.x + threadIdx.x;
    if (i >= N_NODES) return;
    int d = g_deg[i];
    int excl = g_start[i] - d + g_bsumx[i / SCAN_BLOCK];
    g_start[i]  = excl;
    g_cursor[i] = excl;
    float df = (float)d;
    g_dis[i]  = (d > 0) ? rsqrtf(df) : 0.0f;
    g_idis[i] = (d > 0) ? sqrtf(df)  : 0.0f;
}

// Fill CSR: col only (weights folded into states).
__global__ void k_fill(const void* __restrict__ eiv) {
    int e = blockIdx.x * blockDim.x + threadIdx.x;
    if (e >= N_EDGES) return;
    long long r64, c64;
    if (g_not64) {
        const int* ei32 = (const int*)eiv;
        r64 = ei32[e];
        c64 = ei32[N_EDGES + e];
    } else {
        const long long* ei64 = (const long long*)eiv;
        r64 = ei64[e];
        c64 = ei64[(long long)N_EDGES + e];
    }
    if (r64 < 0 || r64 >= N_NODES || c64 < 0 || c64 >= N_NODES) return;
    int r = (int)r64, c = (int)c64;
    int p = atomicAdd(&g_cursor[r], 1);
    g_csr_col[p] = c;
}

// emb' = fp16(dis[n] * emb[n])  — one uint2 (4 halves) per thread
__global__ void k_prescale(const float4* __restrict__ emb,
                           uint2* __restrict__ ep) {
    int i = blockIdx.x * blockDim.x + threadIdx.x;
    if (i >= NF4) return;
    int n = i >> 4;
    float dr = g_dis[n];
    float4 v = __ldcs(&emb[i]);
    uint2 pk;
    pk.x = h2u(__float22half2_rn(make_float2(dr * v.x, dr * v.y)));
    pk.y = h2u(__float22half2_rn(make_float2(dr * v.z, dr * v.w)));
    __stcs(&ep[i], pk);
}

// ---------------------------------------------------------------------------
// Gathers: 16 threads per row, one uint2 (4 halves) lane each.
//   S[r] = sum_{e in row} x'[col]   (pure sum, weights pre-folded)
// Full batches of 16 are compile-time-unrolled (no predication, no dynamic
// bound) so ptxas front-batches all 16 independent LDG.64s -> high MLP.
// ---------------------------------------------------------------------------

__device__ __forceinline__ void gacc(float4& acc, const uint2& hv) {
    float2 f0 = __half22float2(u2h(hv.x));
    float2 f1 = __half22float2(u2h(hv.y));
    acc.x += f0.x; acc.y += f0.y;
    acc.z += f1.x; acc.w += f1.y;
}

__device__ __forceinline__ float4 row_gather_sum(const uint2* __restrict__ x,
                                                 int r, int c, unsigned gmask) {
    int start = g_start[r];
    int end   = g_cursor[r];
    int len   = end - start;
    int nfull = len >> 4;
    float4 acc = make_float4(0.f, 0.f, 0.f, 0.f);

    int base = start;
    for (int b = 0; b < nfull; ++b, base += 16) {
        int cl = __ldcs(&g_csr_col[base + c]);     // unconditional
        uint2 hv[16];
        #pragma unroll
        for (int j = 0; j < 16; ++j) {
            int col = __shfl_sync(gmask, cl, j, 16);
            hv[j] = __ldg(&x[col * 16 + c]);
        }
        #pragma unroll
        for (int j = 0; j < 16; ++j) gacc(acc, hv[j]);
    }
    int rem = len & 15;
    if (rem) {
        int cl = 0;
        if (c < rem) cl = __ldcs(&g_csr_col[base + c]);
        for (int j = 0; j < rem; ++j) {
            int col = __shfl_sync(gmask, cl, j, 16);
            uint2 hv = __ldg(&x[col * 16 + c]);
            gacc(acc, hv);
        }
    }
    return acc;
}

// Layers 1..2: y'[r] = fp16(dis[r]^2 * S)
__global__ void k_gather(const uint2* __restrict__ x,
                         uint2* __restrict__ y) {
    int t = blockIdx.x * blockDim.x + threadIdx.x;   // 4,096,000 threads exact
    int r = t >> 4;
    int c = t & 15;
    if (r >= N_NODES) return;
    unsigned gmask = 0xFFFFu << (threadIdx.x & 16);
    float4 acc = row_gather_sum(x, r, c, gmask);
    float dr = g_dis[r];
    float s = dr * dr;
    uint2 pk;
    pk.x = h2u(__float22half2_rn(make_float2(s * acc.x, s * acc.y)));
    pk.y = h2u(__float22half2_rn(make_float2(s * acc.z, s * acc.w)));
    __stcs(&y[r * 16 + c], pk);
}

// Layer 3 + fused epilogue: out = 0.25*(emb + idis[r]*(y1'+y2') + dis[r]*S3)
__global__ void k_gather_final(const uint2* __restrict__ y2,
                               const float4* __restrict__ emb,
                               const uint2* __restrict__ y1,
                               float4* __restrict__ out) {
    int t = blockIdx.x * blockDim.x + threadIdx.x;
    int r = t >> 4;
    int c = t & 15;
    if (r >= N_NODES) return;
    unsigned gmask = 0xFFFFu << (threadIdx.x & 16);
    float4 acc = row_gather_sum(y2, r, c, gmask);
    float dr = g_dis[r];
    float ir = g_idis[r];
    int idx = r * 16 + c;
    float4 e0 = __ldcs(&emb[idx]);
    uint2 h1 = __ldcs(&y1[idx]);
    uint2 h2 = __ldcs(&y2[idx]);
    float2 a1lo = __half22float2(u2h(h1.x));
    float2 a1hi = __half22float2(u2h(h1.y));
    float2 a2lo = __half22float2(u2h(h2.x));
    float2 a2hi = __half22float2(u2h(h2.y));
    float4 o;
    o.x = 0.25f * (e0.x + ir * (a1lo.x + a2lo.x) + dr * acc.x);
    o.y = 0.25f * (e0.y + ir * (a1lo.y + a2lo.y) + dr * acc.y);
    o.z = 0.25f * (e0.z + ir * (a1hi.x + a2hi.x) + dr * acc.z);
    o.w = 0.25f * (e0.w + ir * (a1hi.y + a2hi.y) + dr * acc.w);
    __stcs(&out[idx], o);
}

// ---------------------------------------------------------------------------

extern "C" void kernel_launch(void* const* d_in, const int* in_sizes, int n_in,
                              void* d_out, int out_size) {
    // Input-order detection by element count (dtype-independent).
    int ei_idx = 1, emb_idx = 0;
    if (n_in >= 2 && in_sizes[0] == 2 * N_EDGES) { ei_idx = 0; emb_idx = 1; }

    const float* emb = (const float*)d_in[emb_idx];
    const void*  ei  = d_in[ei_idx];
    float*       out = (float*)d_out;

    const int TB = 256;
    const int node_blocks = (N_NODES + TB - 1) / TB;
    const int edge_blocks = (N_EDGES + TB - 1) / TB;
    const int f4_blocks   = (NF4 + TB - 1) / TB;
    const int gat_blocks  = (N_NODES * 16 + TB - 1) / TB;   // 4M threads

    __half* e;   cudaGetSymbolAddress((void**)&e,  g_e);
    __half* h1;  cudaGetSymbolAddress((void**)&h1, g_h1);
    __half* h2;  cudaGetSymbolAddress((void**)&h2, g_h2);
    int* not64p; cudaGetSymbolAddress((void**)&not64p, g_not64);

    // ---- preprocess: degrees, scan(+dis), CSR, fp16 prescaled emb ----
    cudaMemsetAsync(not64p, 0, sizeof(int));   // race-free g_not64 reset
    k_zero_detect<<<node_blocks, TB>>>((const long long*)ei);
    k_deg<<<edge_blocks, TB>>>(ei);
    k_scan1<<<NBLK, SCAN_BLOCK>>>();
    k_scan2<<<1, 256>>>();
    k_scan3<<<node_blocks, TB>>>();
    k_fill<<<edge_blocks, TB>>>(ei);
    k_prescale<<<f4_blocks, TB>>>((const float4*)emb, (uint2*)e);

    // ---- 3 gather layers; epilogue fused into the last ----
    k_gather<<<gat_blocks, TB>>>((const uint2*)e,  (uint2*)h1);   // y1'
    k_gather<<<gat_blocks, TB>>>((const uint2*)h1, (uint2*)h2);   // y2'
    k_gather_final<<<gat_blocks, TB>>>((const uint2*)h2,
                                       (const float4*)emb,
                                       (const uint2*)h1,
                                       (float4*)out);
}

// round 14
// speedup vs baseline: 1.6850x; 1.6850x over previous
#include <cuda_runtime.h>
#include <cuda_fp16.h>
#include <cstdint>

// ---------------------------------------------------------------------------
// LightGCN on B200 (sm_100a) — CSR-gather, fp16 folded-weight states,
// 16-lane/row uint2 gathers (R9 shape — measured best; FROZEN).
//   Trick: store x'[c] = dis[c]*x[c] (fp16). Gather = pure sum S = sum x'[col].
//   y'_{l+1}[r] = dis[r]^2 * S. Epilogue: x_l[r] = idis[r]*y'_l[r].
//   CSR holds only col (4 B/edge). Math fp32; storage fp16.
// ---------------------------------------------------------------------------

#define NUM_USERS   100000
#define NUM_ST      150000
#define NUM_INTENTS 6000
#define N_NODES     (NUM_USERS + NUM_ST + NUM_INTENTS)   // 256000
#define EMBED_DIM   64
#define N_EDGES     4000000

#define NFLOATS     (N_NODES * EMBED_DIM)        // 16,384,000
#define NF4         (NFLOATS / 4)                // 4,096,000
#define DETECT_N    4096

#define SCAN_BLOCK  1024
#define NBLK        (N_NODES / SCAN_BLOCK)       // 250 (exact)

#define TB          256
#define EDGE_BLOCKS ((N_EDGES + TB - 1) / TB)    // 15625
#define F4_BLOCKS   ((NF4 + TB - 1) / TB)        // 16000

// half2 <-> u32 reinterpret helpers
__device__ __forceinline__ unsigned h2u(__half2 h) {
    return *reinterpret_cast<unsigned*>(&h);
}
__device__ __forceinline__ __half2 u2h(unsigned u) {
    return *reinterpret_cast<__half2*>(&u);
}

// Scratch (device globals: allocation-guard safe)
__device__ __align__(16) __half g_e [NFLOATS];   // emb' = dis*emb   (fp16)
__device__ __align__(16) __half g_h1[NFLOATS];   // y1' = dis*x1     (fp16)
__device__ __align__(16) __half g_h2[NFLOATS];   // y2' = dis*x2     (fp16)
__device__ float g_dis [N_NODES];    // deg^-1/2 (0 if deg==0)
__device__ float g_idis[N_NODES];    // deg^+1/2 (0 if deg==0)
__device__ int   g_deg[N_NODES];
__device__ int   g_start[N_NODES];     // CSR row start (exclusive scan)
__device__ int   g_cursor[N_NODES];    // fill cursor; after fill = row end
__device__ int   g_bsum[NBLK];
__device__ int   g_bsumx[NBLK];
__device__ int   g_csr_col[N_EDGES];   // col only (4 B/edge)
__device__ int   g_not64;   // 1 => edge data is int32 (zeroed via memset)

// ---------------------------------------------------------------------------

// Zero degrees + dtype detection (g_not64 pre-zeroed by cudaMemsetAsync).
// Genuine int64 indices all lie in [0, N_NODES); int32 data read as int64
// fuses two indices -> value >= 2^32 almost surely.
__global__ void k_zero_detect(const long long* __restrict__ ei) {
    int i = blockIdx.x * blockDim.x + threadIdx.x;
    if (i < N_NODES) g_deg[i] = 0;
    if (i < DETECT_N) {
        long long v = ei[i];
        if (v < 0 || v >= N_NODES) atomicOr(&g_not64, 1);
    }
}

// Degree histogram straight from edge_index (row half only).
__global__ void k_deg(const void* __restrict__ eiv) {
    int e = blockIdx.x * blockDim.x + threadIdx.x;
    if (e >= N_EDGES) return;
    long long r64;
    if (g_not64) r64 = ((const int*)eiv)[e];
    else         r64 = ((const long long*)eiv)[e];
    if (r64 >= 0 && r64 < N_NODES) atomicAdd(&g_deg[(int)r64], 1);
}

// ---- exclusive prefix sum over g_deg ----

__global__ void k_scan1() {
    __shared__ int sh[SCAN_BLOCK];
    int i = blockIdx.x * SCAN_BLOCK + threadIdx.x;
    int v = g_deg[i];
    sh[threadIdx.x] = v;
    __syncthreads();
    for (int off = 1; off < SCAN_BLOCK; off <<= 1) {
        int t = (threadIdx.x >= off) ? sh[threadIdx.x - off] : 0;
        __syncthreads();
        sh[threadIdx.x] += t;
        __syncthreads();
    }
    g_start[i] = sh[threadIdx.x];   // inclusive-within-block (temp)
    if (threadIdx.x == SCAN_BLOCK - 1) g_bsum[blockIdx.x] = sh[threadIdx.x];
}

__global__ void k_scan2() {   // single block of 256 threads, NBLK=250
    __shared__ int sh[256];
    int v = (threadIdx.x < NBLK) ? g_bsum[threadIdx.x] : 0;
    sh[threadIdx.x] = v;
    __syncthreads();
    for (int off = 1; off < 256; off <<= 1) {
        int t = (threadIdx.x >= off) ? sh[threadIdx.x - off] : 0;
        __syncthreads();
        sh[threadIdx.x] += t;
        __syncthreads();
    }
    if (threadIdx.x < NBLK) g_bsumx[threadIdx.x] = sh[threadIdx.x] - v; // exclusive
}

// scan fixup + dis/idis (merged; deg already at hand)
__global__ void k_scan3() {
    int i = blockIdx.x * blockDim.x + threadIdx.x;
    if (i >= N_NODES) return;
    int d = g_deg[i];
    int excl = g_start[i] - d + g_bsumx[i / SCAN_BLOCK];
    g_start[i]  = excl;
    g_cursor[i] = excl;
    float df = (float)d;
    g_dis[i]  = (d > 0) ? rsqrtf(df) : 0.0f;
    g_idis[i] = (d > 0) ? sqrtf(df)  : 0.0f;
}

// Merged CSR-fill + emb-prescale (both depend only on scan3).
// Blocks [0, EDGE_BLOCKS) do fill; blocks [EDGE_BLOCKS, +F4_BLOCKS) prescale.
__global__ void k_fill_prescale(const void* __restrict__ eiv,
                                const float4* __restrict__ emb,
                                uint2* __restrict__ ep) {
    if (blockIdx.x < EDGE_BLOCKS) {
        // ---- fill CSR: col only ----
        int e = blockIdx.x * blockDim.x + threadIdx.x;
        if (e >= N_EDGES) return;
        long long r64, c64;
        if (g_not64) {
            const int* ei32 = (const int*)eiv;
            r64 = ei32[e];
            c64 = ei32[N_EDGES + e];
        } else {
            const long long* ei64 = (const long long*)eiv;
            r64 = ei64[e];
            c64 = ei64[(long long)N_EDGES + e];
        }
        if (r64 < 0 || r64 >= N_NODES || c64 < 0 || c64 >= N_NODES) return;
        int r = (int)r64, c = (int)c64;
        int p = atomicAdd(&g_cursor[r], 1);
        g_csr_col[p] = c;
    } else {
        // ---- emb' = fp16(dis[n] * emb[n]) ----
        int i = (blockIdx.x - EDGE_BLOCKS) * blockDim.x + threadIdx.x;
        if (i >= NF4) return;
        int n = i >> 4;
        float dr = g_dis[n];
        float4 v = __ldcs(&emb[i]);
        uint2 pk;
        pk.x = h2u(__float22half2_rn(make_float2(dr * v.x, dr * v.y)));
        pk.y = h2u(__float22half2_rn(make_float2(dr * v.z, dr * v.w)));
        __stcs(&ep[i], pk);
    }
}

// ---------------------------------------------------------------------------
// Gathers: 16 threads per row, one uint2 (4 halves) lane each.
//   S[r] = sum_{e in row} x'[col]   (pure sum, weights pre-folded)
// (R9 structure verbatim — measured best; FROZEN.)
// ---------------------------------------------------------------------------

__device__ __forceinline__ float4 row_gather_sum(const uint2* __restrict__ x,
                                                 int r, int c, unsigned gmask) {
    int start = g_start[r];
    int end   = g_cursor[r];
    float4 acc = make_float4(0.f, 0.f, 0.f, 0.f);
    for (int base = start; base < end; base += 16) {
        int n = min(16, end - base);
        int cl = 0;
        if (c < n) cl = __ldcs(&g_csr_col[base + c]);
        #pragma unroll 4
        for (int j = 0; j < n; ++j) {
            int col  = __shfl_sync(gmask, cl, j, 16);
            uint2 hv = __ldg(&x[col * 16 + c]);
            float2 f0 = __half22float2(u2h(hv.x));
            float2 f1 = __half22float2(u2h(hv.y));
            acc.x += f0.x; acc.y += f0.y;
            acc.z += f1.x; acc.w += f1.y;
        }
    }
    return acc;
}

// Layers 1..2: y'[r] = fp16(dis[r]^2 * S)
__global__ void k_gather(const uint2* __restrict__ x,
                         uint2* __restrict__ y) {
    int t = blockIdx.x * blockDim.x + threadIdx.x;   // 4,096,000 threads exact
    int r = t >> 4;
    int c = t & 15;
    if (r >= N_NODES) return;
    unsigned gmask = 0xFFFFu << (threadIdx.x & 16);
    float4 acc = row_gather_sum(x, r, c, gmask);
    float dr = g_dis[r];
    float s = dr * dr;
    uint2 pk;
    pk.x = h2u(__float22half2_rn(make_float2(s * acc.x, s * acc.y)));
    pk.y = h2u(__float22half2_rn(make_float2(s * acc.z, s * acc.w)));
    __stcs(&y[r * 16 + c], pk);
}

// Layer 3 + fused epilogue: out = 0.25*(emb + idis[r]*(y1'+y2') + dis[r]*S3)
__global__ void k_gather_final(const uint2* __restrict__ y2,
                               const float4* __restrict__ emb,
                               const uint2* __restrict__ y1,
                               float4* __restrict__ out) {
    int t = blockIdx.x * blockDim.x + threadIdx.x;
    int r = t >> 4;
    int c = t & 15;
    if (r >= N_NODES) return;
    unsigned gmask = 0xFFFFu << (threadIdx.x & 16);
    float4 acc = row_gather_sum(y2, r, c, gmask);
    float dr = g_dis[r];
    float ir = g_idis[r];
    int idx = r * 16 + c;
    float4 e0 = __ldcs(&emb[idx]);
    uint2 h1 = __ldcs(&y1[idx]);
    uint2 h2 = __ldcs(&y2[idx]);
    float2 a1lo = __half22float2(u2h(h1.x));
    float2 a1hi = __half22float2(u2h(h1.y));
    float2 a2lo = __half22float2(u2h(h2.x));
    float2 a2hi = __half22float2(u2h(h2.y));
    float4 o;
    o.x = 0.25f * (e0.x + ir * (a1lo.x + a2lo.x) + dr * acc.x);
    o.y = 0.25f * (e0.y + ir * (a1lo.y + a2lo.y) + dr * acc.y);
    o.z = 0.25f * (e0.z + ir * (a1hi.x + a2hi.x) + dr * acc.z);
    o.w = 0.25f * (e0.w + ir * (a1hi.y + a2hi.y) + dr * acc.w);
    __stcs(&out[idx], o);
}

// ---------------------------------------------------------------------------

extern "C" void kernel_launch(void* const* d_in, const int* in_sizes, int n_in,
                              void* d_out, int out_size) {
    // Input-order detection by element count (dtype-independent).
    int ei_idx = 1, emb_idx = 0;
    if (n_in >= 2 && in_sizes[0] == 2 * N_EDGES) { ei_idx = 0; emb_idx = 1; }

    const float* emb = (const float*)d_in[emb_idx];
    const void*  ei  = d_in[ei_idx];
    float*       out = (float*)d_out;

    const int node_blocks = (N_NODES + TB - 1) / TB;
    const int gat_blocks  = (N_NODES * 16 + TB - 1) / TB;   // 4M threads

    __half* e;   cudaGetSymbolAddress((void**)&e,  g_e);
    __half* h1;  cudaGetSymbolAddress((void**)&h1, g_h1);
    __half* h2;  cudaGetSymbolAddress((void**)&h2, g_h2);
    int* not64p; cudaGetSymbolAddress((void**)&not64p, g_not64);

    // ---- preprocess: degrees, scan(+dis), CSR fill + fp16 emb' (merged) ----
    cudaMemsetAsync(not64p, 0, sizeof(int));   // race-free g_not64 reset
    k_zero_detect<<<node_blocks, TB>>>((const long long*)ei);
    k_deg<<<EDGE_BLOCKS, TB>>>(ei);
    k_scan1<<<NBLK, SCAN_BLOCK>>>();
    k_scan2<<<1, 256>>>();
    k_scan3<<<node_blocks, TB>>>();
    k_fill_prescale<<<EDGE_BLOCKS + F4_BLOCKS, TB>>>(ei, (const float4*)emb,
                                                     (uint2*)e);

    // ---- 3 gather layers; epilogue fused into the last ----
    k_gather<<<gat_blocks, TB>>>((const uint2*)e,  (uint2*)h1);   // y1'
    k_gather<<<gat_blocks, TB>>>((const uint2*)h1, (uint2*)h2);   // y2'
    k_gather_final<<<gat_blocks, TB>>>((const uint2*)h2,
                                       (const float4*)emb,
                                       (const uint2*)h1,
                                       (float4*)out);
}